// round 16
// baseline (speedup 1.0000x reference)
#include <cuda_runtime.h>

#define BATCH 2048
#define T 128
#define NS 16
#define MS 8
#define CS 4
#define DT 0.01f
#define SB 16    // batches per block in staged states
#define BB 32    // batches per block in staged backward

// Batch-independent tables (L2-resident).
__device__ float g_K2[T * NS * MS];             // K[t][i][q]
__device__ float g_Pf[(T - 1) * NS * NS];       // P_f[t]
__device__ float g_G[(T - 1) * NS * NS];        // G[t][i][j]
__device__ float g_sp[(size_t)BATCH * T * NS];  // predicted states (t>=1)

__device__ __forceinline__ float4 ld4(const float* p) { return *reinterpret_cast<const float4*>(p); }
__device__ __forceinline__ void st4(float* p, float4 v) { *reinterpret_cast<float4*>(p) = v; }
__device__ __forceinline__ float rcpa(float x) { float y; asm("rcp.approx.f32 %0, %1;" : "=f"(y) : "f"(x)); return y; }
__device__ __forceinline__ float shfl(float v, int s) { return __shfl_sync(0xffffffffu, v, s); }
__device__ __forceinline__ float shflx(float v, int m) { return __shfl_xor_sync(0xffffffffu, v, m); }
__device__ __forceinline__ float shfl16(float v, int s) { return __shfl_sync(0xffffffffu, v, s, 16); }

// ============================================================================
// Kernel A: Riccati recursion (ONE warp) — R11 measured-best body.
// ============================================================================
__global__ __launch_bounds__(32) void kf_gains(
    const float* __restrict__ P0, const float* __restrict__ A,
    const float* __restrict__ H, const float* __restrict__ Q,
    const float* __restrict__ R)
{
    __shared__ float Fb[16 * 20], Ftb[16 * 20], Qb[16 * 20];
    __shared__ float Hb[8 * 20], Ht[16 * 8], Rb[64];
    __shared__ float P[16 * 20], PHt[16 * 8], X2[8 * 20];

    const int lane = threadIdx.x;
    for (int idx = lane; idx < 256; idx += 32) {
        int i = idx >> 4, k = idx & 15;
        float a = A[idx];
        float f = (i == k ? 1.0f : 0.0f) + DT * a;
        Fb[i * 20 + k] = f; Ftb[k * 20 + i] = f;
        Qb[i * 20 + k] = Q[idx];
        P[i * 20 + k] = P0[idx];
    }
    for (int idx = lane; idx < 128; idx += 32) {
        int q = idx >> 4, k = idx & 15;
        float h = H[idx];
        Hb[q * 20 + k] = h; Ht[k * 8 + q] = h;
    }
    for (int idx = lane; idx < 64; idx += 32) Rb[idx] = R[idx];
    __syncwarp();

    const int row = lane >> 1, h = lane & 1, j0 = h * 8;
    const int rr = row & 7;

    float frow[16];
    #pragma unroll
    for (int k = 0; k < 16; ++k) frow[k] = Fb[row * 20 + k];

    float a[8], w[8];

    for (int t = 0; t < T; ++t) {
        // W = F * P
        #pragma unroll
        for (int j = 0; j < 8; ++j) w[j] = 0.0f;
        #pragma unroll
        for (int k = 0; k < 16; ++k) {
            float fv = frow[k];
            float4 p0 = ld4(&P[k * 20 + j0]);
            float4 p1 = ld4(&P[k * 20 + j0 + 4]);
            w[0] = fmaf(fv, p0.x, w[0]); w[1] = fmaf(fv, p0.y, w[1]);
            w[2] = fmaf(fv, p0.z, w[2]); w[3] = fmaf(fv, p0.w, w[3]);
            w[4] = fmaf(fv, p1.x, w[4]); w[5] = fmaf(fv, p1.y, w[5]);
            w[6] = fmaf(fv, p1.z, w[6]); w[7] = fmaf(fv, p1.w, w[7]);
        }

        // PP = W * F^T + Q  (regs a[])
        {
            float wk[16];
            #pragma unroll
            for (int j = 0; j < 8; ++j) {
                wk[j0 + j] = w[j];
                wk[(j0 ^ 8) + j] = shflx(w[j], 1);
            }
            float4 q0 = ld4(&Qb[row * 20 + j0]);
            float4 q1 = ld4(&Qb[row * 20 + j0 + 4]);
            a[0] = q0.x; a[1] = q0.y; a[2] = q0.z; a[3] = q0.w;
            a[4] = q1.x; a[5] = q1.y; a[6] = q1.z; a[7] = q1.w;
            #pragma unroll
            for (int k = 0; k < 16; ++k) {
                float wv = wk[k];
                float4 f0 = ld4(&Ftb[k * 20 + j0]);
                float4 f1 = ld4(&Ftb[k * 20 + j0 + 4]);
                a[0] = fmaf(wv, f0.x, a[0]); a[1] = fmaf(wv, f0.y, a[1]);
                a[2] = fmaf(wv, f0.z, a[2]); a[3] = fmaf(wv, f0.w, a[3]);
                a[4] = fmaf(wv, f1.x, a[4]); a[5] = fmaf(wv, f1.y, a[5]);
                a[6] = fmaf(wv, f1.z, a[6]); a[7] = fmaf(wv, f1.w, a[7]);
            }
        }

        // PHt[i][q] = sum_k PP[i][k] * H[q][k]
        {
            float pk[16];
            #pragma unroll
            for (int j = 0; j < 8; ++j) {
                pk[j0 + j] = a[j];
                pk[(j0 ^ 8) + j] = shflx(a[j], 1);
            }
            const int qh = h * 4;
            float4 acc = make_float4(0.f, 0.f, 0.f, 0.f);
            #pragma unroll
            for (int k = 0; k < 16; ++k) {
                float p = pk[k];
                float4 hv = ld4(&Ht[k * 8 + qh]);
                acc.x = fmaf(p, hv.x, acc.x); acc.y = fmaf(p, hv.y, acc.y);
                acc.z = fmaf(p, hv.z, acc.z); acc.w = fmaf(p, hv.w, acc.w);
            }
            st4(&PHt[row * 8 + qh], acc);
        }
        __syncwarp();

        // S rows + RHS into registers
        float s4[4], rhs[8];
        {
            const int ch = h * 4;
            s4[0] = Rb[rr * 8 + ch];     s4[1] = Rb[rr * 8 + ch + 1];
            s4[2] = Rb[rr * 8 + ch + 2]; s4[3] = Rb[rr * 8 + ch + 3];
            #pragma unroll
            for (int k = 0; k < 16; ++k) {
                float hv = Hb[rr * 20 + k];
                float4 ph = ld4(&PHt[k * 8 + ch]);
                s4[0] = fmaf(hv, ph.x, s4[0]); s4[1] = fmaf(hv, ph.y, s4[1]);
                s4[2] = fmaf(hv, ph.z, s4[2]); s4[3] = fmaf(hv, ph.w, s4[3]);
            }
            #pragma unroll
            for (int j = 0; j < 8; ++j)
                rhs[j] = PHt[(h * 8 + j) * 8 + rr];
        }

        // GJ solve S * X2 = PHt^T (8x8); K = X2^T
        {
            #pragma unroll
            for (int p = 0; p < 8; ++p) {
                const int hp = (p >= 4) ? 1 : 0;
                float cand = s4[p & 3];
                float f_num = shfl(cand, (rr << 1) | hp);
                float diag  = shfl(cand, (p << 1) | hp);
                const int src = (p << 1) | h;
                float ps0 = shfl(s4[0], src), ps1 = shfl(s4[1], src);
                float ps2 = shfl(s4[2], src), ps3 = shfl(s4[3], src);
                float pr[8];
                #pragma unroll
                for (int j = 0; j < 8; ++j) pr[j] = shfl(rhs[j], src);
                float f = (rr == p) ? 0.0f : f_num * rcpa(diag);
                s4[0] = fmaf(-f, ps0, s4[0]); s4[1] = fmaf(-f, ps1, s4[1]);
                s4[2] = fmaf(-f, ps2, s4[2]); s4[3] = fmaf(-f, ps3, s4[3]);
                #pragma unroll
                for (int j = 0; j < 8; ++j) rhs[j] = fmaf(-f, pr[j], rhs[j]);
            }
            float s01 = (rr & 1) ? s4[1] : s4[0];
            float s23 = (rr & 1) ? s4[3] : s4[2];
            float cand_r = (rr & 2) ? s23 : s01;
            float diag_r = shfl(cand_r, (rr << 1) | ((rr >= 4) ? 1 : 0));
            float invd = rcpa(diag_r);
            if (lane < 16) {
                st4(&X2[rr * 20 + h * 8],
                    make_float4(rhs[0] * invd, rhs[1] * invd, rhs[2] * invd, rhs[3] * invd));
                st4(&X2[rr * 20 + h * 8 + 4],
                    make_float4(rhs[4] * invd, rhs[5] * invd, rhs[6] * invd, rhs[7] * invd));
                #pragma unroll
                for (int j = 0; j < 8; ++j)
                    g_K2[t * 128 + (h * 8 + j) * 8 + rr] = rhs[j] * invd;
            }
        }
        __syncwarp();

        // P_f = PP - K*(H*PP);  (H*PP)[q][j] = PHt[j][q]
        {
            float kq[8];
            #pragma unroll
            for (int q = 0; q < 8; ++q) kq[q] = X2[q * 20 + row];
            float n[8];
            #pragma unroll
            for (int j = 0; j < 8; ++j) {
                float4 p0 = ld4(&PHt[(j0 + j) * 8]);
                float4 p1 = ld4(&PHt[(j0 + j) * 8 + 4]);
                float v = a[j];
                v = fmaf(-kq[0], p0.x, v); v = fmaf(-kq[1], p0.y, v);
                v = fmaf(-kq[2], p0.z, v); v = fmaf(-kq[3], p0.w, v);
                v = fmaf(-kq[4], p1.x, v); v = fmaf(-kq[5], p1.y, v);
                v = fmaf(-kq[6], p1.z, v); v = fmaf(-kq[7], p1.w, v);
                n[j] = v;
            }
            float4 v0 = make_float4(n[0], n[1], n[2], n[3]);
            float4 v1 = make_float4(n[4], n[5], n[6], n[7]);
            st4(&P[row * 20 + j0], v0);
            st4(&P[row * 20 + j0 + 4], v1);
            if (t < T - 1) {
                st4(&g_Pf[t * 256 + row * 16 + j0], v0);
                st4(&g_Pf[t * 256 + row * 16 + j0 + 4], v1);
            }
        }
        __syncwarp();
    }
}

// ============================================================================
// Kernel B: smoother gains (R11). g_G[t][i][j] row-major.
// ============================================================================
__global__ __launch_bounds__(32) void kf_smoother_gains(
    const float* __restrict__ A, const float* __restrict__ Q)
{
    __shared__ float Fb[16 * 20], Ftb[16 * 20], Qb[16 * 20], Pf[16 * 20];
    const int t = blockIdx.x;
    const int lane = threadIdx.x;

    for (int idx = lane; idx < 256; idx += 32) {
        int i = idx >> 4, k = idx & 15;
        float av = A[idx];
        float f = (i == k ? 1.0f : 0.0f) + DT * av;
        Fb[i * 20 + k] = f; Ftb[k * 20 + i] = f;
        Qb[i * 20 + k] = Q[idx];
        Pf[i * 20 + k] = g_Pf[t * 256 + idx];
    }
    __syncwarp();

    const int row = lane >> 1, h = lane & 1, j0 = h * 8;
    float frow[16];
    #pragma unroll
    for (int k = 0; k < 16; ++k) frow[k] = Fb[row * 20 + k];

    float a[8], w[8];
    #pragma unroll
    for (int j = 0; j < 8; ++j) w[j] = 0.0f;
    #pragma unroll
    for (int k = 0; k < 16; ++k) {
        float fv = frow[k];
        float4 p0 = ld4(&Pf[k * 20 + j0]);
        float4 p1 = ld4(&Pf[k * 20 + j0 + 4]);
        w[0] = fmaf(fv, p0.x, w[0]); w[1] = fmaf(fv, p0.y, w[1]);
        w[2] = fmaf(fv, p0.z, w[2]); w[3] = fmaf(fv, p0.w, w[3]);
        w[4] = fmaf(fv, p1.x, w[4]); w[5] = fmaf(fv, p1.y, w[5]);
        w[6] = fmaf(fv, p1.z, w[6]); w[7] = fmaf(fv, p1.w, w[7]);
    }
    {
        float wk[16];
        #pragma unroll
        for (int j = 0; j < 8; ++j) {
            wk[j0 + j] = w[j];
            wk[(j0 ^ 8) + j] = shflx(w[j], 1);
        }
        float4 q0 = ld4(&Qb[row * 20 + j0]);
        float4 q1 = ld4(&Qb[row * 20 + j0 + 4]);
        a[0] = q0.x; a[1] = q0.y; a[2] = q0.z; a[3] = q0.w;
        a[4] = q1.x; a[5] = q1.y; a[6] = q1.z; a[7] = q1.w;
        #pragma unroll
        for (int k = 0; k < 16; ++k) {
            float wv = wk[k];
            float4 f0 = ld4(&Ftb[k * 20 + j0]);
            float4 f1 = ld4(&Ftb[k * 20 + j0 + 4]);
            a[0] = fmaf(wv, f0.x, a[0]); a[1] = fmaf(wv, f0.y, a[1]);
            a[2] = fmaf(wv, f0.z, a[2]); a[3] = fmaf(wv, f0.w, a[3]);
            a[4] = fmaf(wv, f1.x, a[4]); a[5] = fmaf(wv, f1.y, a[5]);
            a[6] = fmaf(wv, f1.z, a[6]); a[7] = fmaf(wv, f1.w, a[7]);
        }
    }
    #pragma unroll
    for (int p = 0; p < 16; ++p) {
        const int hp = (p >= 8) ? 1 : 0;
        float cand = a[p & 7];
        float f_num = shfl(cand, (row << 1) | hp);
        float diag  = shfl(cand, (p << 1) | hp);
        const int src = (p << 1) | h;
        float pa[8], pw[8];
        #pragma unroll
        for (int j = 0; j < 8; ++j) { pa[j] = shfl(a[j], src); pw[j] = shfl(w[j], src); }
        float f = (row == p) ? 0.0f : f_num * rcpa(diag);
        #pragma unroll
        for (int j = 0; j < 8; ++j) {
            a[j] = fmaf(-f, pa[j], a[j]);
            w[j] = fmaf(-f, pw[j], w[j]);
        }
    }
    const int ri = row & 7;
    float s01 = (ri & 1) ? a[1] : a[0];
    float s23 = (ri & 1) ? a[3] : a[2];
    float s45 = (ri & 1) ? a[5] : a[4];
    float s67 = (ri & 1) ? a[7] : a[6];
    float t0 = (ri & 2) ? s23 : s01;
    float t1 = (ri & 2) ? s67 : s45;
    float cand_r = (ri & 4) ? t1 : t0;
    float diag_r = shfl(cand_r, (row << 1) | ((row >= 8) ? 1 : 0));
    float invd = rcpa(diag_r);
    #pragma unroll
    for (int j = 0; j < 8; ++j)
        g_G[t * 256 + (j0 + j) * 16 + row] = w[j] * invd;
}

// ============================================================================
// Kernel C: forward state filter, smem-staged (measured best).
// ============================================================================
__global__ __launch_bounds__(256) void kf_states(
    const float* __restrict__ state0, const float* __restrict__ controls,
    const float* __restrict__ obs, const float* __restrict__ A,
    const float* __restrict__ Bc, const float* __restrict__ H,
    float* __restrict__ out)
{
    extern __shared__ float sm[];
    float* Ks = sm;
    float* us = Ks + T * 128;
    float* ys = us + SB * T * 4;

    const int tid = threadIdx.x;
    const int b0 = blockIdx.x * SB;

    for (int idx = tid; idx < 4096; idx += 256)
        st4(&Ks[idx * 4], ld4(&g_K2[idx * 4]));
    {
        const float* src = controls + (size_t)b0 * T * 4;
        for (int idx = tid; idx < 2048; idx += 256)
            st4(&us[idx * 4], ld4(&src[idx * 4]));
    }
    {
        const float* src = obs + (size_t)b0 * T * 8;
        for (int idx = tid; idx < 4096; idx += 256)
            st4(&ys[idx * 4], ld4(&src[idx * 4]));
    }
    __syncthreads();

    const int L = tid & 31;
    const int bl = (tid >> 5) * 2 + (L >> 4);
    const int b = b0 + bl;
    const int i = L & 15;

    float arow[16], hrow[16], brow[4];
    #pragma unroll
    for (int k = 0; k < 16; ++k) arow[k] = A[i * 16 + k];
    #pragma unroll
    for (int k = 0; k < 16; ++k) hrow[k] = H[(i & 7) * 16 + k];
    #pragma unroll
    for (int c = 0; c < 4; ++c) brow[c] = Bc[i * 4 + c];

    float s = state0[b * 16 + i];

    #pragma unroll 1
    for (int t = 0; t < T; ++t) {
        float4 uu = ld4(&us[bl * 512 + t * 4]);
        float4 k0 = ld4(&Ks[t * 128 + i * 8]);
        float4 k1 = ld4(&Ks[t * 128 + i * 8 + 4]);
        float yv = ys[bl * 1024 + t * 8 + (i & 7)];

        float a0 = 0.0f, a1 = 0.0f;
        #pragma unroll
        for (int k = 0; k < 8; ++k) {
            a0 = fmaf(arow[k], shfl16(s, k), a0);
            a1 = fmaf(arow[k + 8], shfl16(s, k + 8), a1);
        }
        a0 = fmaf(brow[0], uu.x, a0); a0 = fmaf(brow[1], uu.y, a0);
        a0 = fmaf(brow[2], uu.z, a0); a0 = fmaf(brow[3], uu.w, a0);
        float sp = s + DT * (a0 + a1);
        if (t > 0) g_sp[((size_t)b * T + t) * NS + i] = sp;

        float h0 = 0.0f, h1 = 0.0f;
        #pragma unroll
        for (int k = 0; k < 8; ++k) {
            h0 = fmaf(hrow[k], shfl16(sp, k), h0);
            h1 = fmaf(hrow[k + 8], shfl16(sp, k + 8), h1);
        }
        float iv = yv - (h0 + h1);

        float acc = sp;
        acc = fmaf(k0.x, shfl16(iv, 0), acc);
        acc = fmaf(k0.y, shfl16(iv, 1), acc);
        acc = fmaf(k0.z, shfl16(iv, 2), acc);
        acc = fmaf(k0.w, shfl16(iv, 3), acc);
        acc = fmaf(k1.x, shfl16(iv, 4), acc);
        acc = fmaf(k1.y, shfl16(iv, 5), acc);
        acc = fmaf(k1.z, shfl16(iv, 6), acc);
        acc = fmaf(k1.w, shfl16(iv, 7), acc);
        s = acc;
        out[((size_t)b * T + t) * NS + i] = s;
    }
}

// ============================================================================
// Kernel D: backward smoother, G staged in smem ROW-MAJOR (4x LDS.128/step).
// 512 threads = 16 warps share one 130KB staged copy; 64 blocks x 32 batches.
// ============================================================================
__global__ __launch_bounds__(512) void kf_backward(float* __restrict__ out)
{
    extern __shared__ float Gs[];   // (T-1)*256 floats = 130048 B

    const int tid = threadIdx.x;
    for (int idx = tid; idx < (T - 1) * 64; idx += 512)
        st4(&Gs[idx * 4], ld4(&g_G[idx * 4]));
    __syncthreads();

    const int L = tid & 31;
    const int gw = blockIdx.x * 16 + (tid >> 5);
    const int b = gw * 2 + (L >> 4);
    const int i = L & 15;

    float ss = out[((size_t)b * T + (T - 1)) * NS + i];
    float xc[16];
    {
        const float* gp = &Gs[(T - 2) * 256 + i * 16];
        float4 g0 = ld4(gp), g1 = ld4(gp + 4), g2 = ld4(gp + 8), g3 = ld4(gp + 12);
        xc[0] = g0.x; xc[1] = g0.y; xc[2] = g0.z; xc[3] = g0.w;
        xc[4] = g1.x; xc[5] = g1.y; xc[6] = g1.z; xc[7] = g1.w;
        xc[8] = g2.x; xc[9] = g2.y; xc[10] = g2.z; xc[11] = g2.w;
        xc[12] = g3.x; xc[13] = g3.y; xc[14] = g3.z; xc[15] = g3.w;
    }
    float spn_c = g_sp[((size_t)b * T + (T - 1)) * NS + i];
    float sf_c  = out[((size_t)b * T + (T - 2)) * NS + i];

    #pragma unroll 1
    for (int t = T - 2; t >= 0; --t) {
        float xn[16]; float spn_n = 0.0f, sf_n = 0.0f;
        if (t > 0) {
            const float* gp = &Gs[(t - 1) * 256 + i * 16];
            float4 g0 = ld4(gp), g1 = ld4(gp + 4), g2 = ld4(gp + 8), g3 = ld4(gp + 12);
            xn[0] = g0.x; xn[1] = g0.y; xn[2] = g0.z; xn[3] = g0.w;
            xn[4] = g1.x; xn[5] = g1.y; xn[6] = g1.z; xn[7] = g1.w;
            xn[8] = g2.x; xn[9] = g2.y; xn[10] = g2.z; xn[11] = g2.w;
            xn[12] = g3.x; xn[13] = g3.y; xn[14] = g3.z; xn[15] = g3.w;
            spn_n = g_sp[((size_t)b * T + t) * NS + i];
            sf_n  = out[((size_t)b * T + t - 1) * NS + i];
        }
        float d = ss - spn_c;
        float m0 = 0.0f, m1 = 0.0f;
        #pragma unroll
        for (int j = 0; j < 8; ++j) {
            m0 = fmaf(shfl16(d, j), xc[j], m0);
            m1 = fmaf(shfl16(d, j + 8), xc[j + 8], m1);
        }
        ss = sf_c + m0 + m1;
        out[((size_t)b * T + t) * NS + i] = ss;
        if (t > 0) {
            #pragma unroll
            for (int j = 0; j < 16; ++j) xc[j] = xn[j];
            spn_c = spn_n; sf_c = sf_n;
        }
    }
}

extern "C" void kernel_launch(void* const* d_in, const int* in_sizes, int n_in,
                              void* d_out, int out_size) {
    (void)in_sizes; (void)n_in; (void)out_size;
    const float* state0   = (const float*)d_in[0];
    const float* P0       = (const float*)d_in[1];
    const float* controls = (const float*)d_in[2];
    const float* obs      = (const float*)d_in[3];
    const float* A        = (const float*)d_in[4];
    const float* Bc       = (const float*)d_in[5];
    const float* H        = (const float*)d_in[6];
    const float* Q        = (const float*)d_in[7];
    const float* R        = (const float*)d_in[8];
    float* out = (float*)d_out;

    const int smem_states   = (T * 128 + SB * T * 4 + SB * T * 8) * 4;   // 163840 B
    const int smem_backward = (T - 1) * 256 * 4;                         // 130048 B
    cudaFuncSetAttribute(kf_states,   cudaFuncAttributeMaxDynamicSharedMemorySize, smem_states);
    cudaFuncSetAttribute(kf_backward, cudaFuncAttributeMaxDynamicSharedMemorySize, smem_backward);

    kf_gains<<<1, 32>>>(P0, A, H, Q, R);
    kf_smoother_gains<<<T - 1, 32>>>(A, Q);
    kf_states<<<BATCH / SB, 256, smem_states>>>(state0, controls, obs, A, Bc, H, out);
    kf_backward<<<BATCH / BB, 512, smem_backward>>>(out);
}

// round 17
// speedup vs baseline: 1.1379x; 1.1379x over previous
#include <cuda_runtime.h>

#define BATCH 2048
#define T 128
#define NS 16
#define MS 8
#define CS 4
#define DT 0.01f
#define SB 16    // batches per block in staged states

// Batch-independent tables (L2-resident).
__device__ float g_K2[T * NS * MS];             // K[t][i][q]
__device__ float g_Pf[(T - 1) * NS * NS];       // P_f[t]
__device__ float g_G[(T - 1) * NS * NS];        // G[t][i][j]
// Per-(b,t) filter results: [0..15]=s_f, [16..31]=s_p  (one 128B line each)
__device__ float g_fp[(size_t)BATCH * T * 32];

__device__ __forceinline__ float4 ld4(const float* p) { return *reinterpret_cast<const float4*>(p); }
__device__ __forceinline__ void st4(float* p, float4 v) { *reinterpret_cast<float4*>(p) = v; }
__device__ __forceinline__ float rcpa(float x) { float y; asm("rcp.approx.f32 %0, %1;" : "=f"(y) : "f"(x)); return y; }
__device__ __forceinline__ float shfl(float v, int s) { return __shfl_sync(0xffffffffu, v, s); }
__device__ __forceinline__ float shflx(float v, int m) { return __shfl_xor_sync(0xffffffffu, v, m); }
__device__ __forceinline__ float shfl16(float v, int s) { return __shfl_sync(0xffffffffu, v, s, 16); }

// ============================================================================
// Kernel A: Riccati recursion (ONE warp) — R11 measured-best body.
// ============================================================================
__global__ __launch_bounds__(32) void kf_gains(
    const float* __restrict__ P0, const float* __restrict__ A,
    const float* __restrict__ H, const float* __restrict__ Q,
    const float* __restrict__ R)
{
    __shared__ float Fb[16 * 20], Ftb[16 * 20], Qb[16 * 20];
    __shared__ float Hb[8 * 20], Ht[16 * 8], Rb[64];
    __shared__ float P[16 * 20], PHt[16 * 8], X2[8 * 20];

    const int lane = threadIdx.x;
    for (int idx = lane; idx < 256; idx += 32) {
        int i = idx >> 4, k = idx & 15;
        float a = A[idx];
        float f = (i == k ? 1.0f : 0.0f) + DT * a;
        Fb[i * 20 + k] = f; Ftb[k * 20 + i] = f;
        Qb[i * 20 + k] = Q[idx];
        P[i * 20 + k] = P0[idx];
    }
    for (int idx = lane; idx < 128; idx += 32) {
        int q = idx >> 4, k = idx & 15;
        float h = H[idx];
        Hb[q * 20 + k] = h; Ht[k * 8 + q] = h;
    }
    for (int idx = lane; idx < 64; idx += 32) Rb[idx] = R[idx];
    __syncwarp();

    const int row = lane >> 1, h = lane & 1, j0 = h * 8;
    const int rr = row & 7;

    float frow[16];
    #pragma unroll
    for (int k = 0; k < 16; ++k) frow[k] = Fb[row * 20 + k];

    float a[8], w[8];

    for (int t = 0; t < T; ++t) {
        // W = F * P
        #pragma unroll
        for (int j = 0; j < 8; ++j) w[j] = 0.0f;
        #pragma unroll
        for (int k = 0; k < 16; ++k) {
            float fv = frow[k];
            float4 p0 = ld4(&P[k * 20 + j0]);
            float4 p1 = ld4(&P[k * 20 + j0 + 4]);
            w[0] = fmaf(fv, p0.x, w[0]); w[1] = fmaf(fv, p0.y, w[1]);
            w[2] = fmaf(fv, p0.z, w[2]); w[3] = fmaf(fv, p0.w, w[3]);
            w[4] = fmaf(fv, p1.x, w[4]); w[5] = fmaf(fv, p1.y, w[5]);
            w[6] = fmaf(fv, p1.z, w[6]); w[7] = fmaf(fv, p1.w, w[7]);
        }

        // PP = W * F^T + Q  (regs a[])
        {
            float wk[16];
            #pragma unroll
            for (int j = 0; j < 8; ++j) {
                wk[j0 + j] = w[j];
                wk[(j0 ^ 8) + j] = shflx(w[j], 1);
            }
            float4 q0 = ld4(&Qb[row * 20 + j0]);
            float4 q1 = ld4(&Qb[row * 20 + j0 + 4]);
            a[0] = q0.x; a[1] = q0.y; a[2] = q0.z; a[3] = q0.w;
            a[4] = q1.x; a[5] = q1.y; a[6] = q1.z; a[7] = q1.w;
            #pragma unroll
            for (int k = 0; k < 16; ++k) {
                float wv = wk[k];
                float4 f0 = ld4(&Ftb[k * 20 + j0]);
                float4 f1 = ld4(&Ftb[k * 20 + j0 + 4]);
                a[0] = fmaf(wv, f0.x, a[0]); a[1] = fmaf(wv, f0.y, a[1]);
                a[2] = fmaf(wv, f0.z, a[2]); a[3] = fmaf(wv, f0.w, a[3]);
                a[4] = fmaf(wv, f1.x, a[4]); a[5] = fmaf(wv, f1.y, a[5]);
                a[6] = fmaf(wv, f1.z, a[6]); a[7] = fmaf(wv, f1.w, a[7]);
            }
        }

        // PHt[i][q] = sum_k PP[i][k] * H[q][k]
        {
            float pk[16];
            #pragma unroll
            for (int j = 0; j < 8; ++j) {
                pk[j0 + j] = a[j];
                pk[(j0 ^ 8) + j] = shflx(a[j], 1);
            }
            const int qh = h * 4;
            float4 acc = make_float4(0.f, 0.f, 0.f, 0.f);
            #pragma unroll
            for (int k = 0; k < 16; ++k) {
                float p = pk[k];
                float4 hv = ld4(&Ht[k * 8 + qh]);
                acc.x = fmaf(p, hv.x, acc.x); acc.y = fmaf(p, hv.y, acc.y);
                acc.z = fmaf(p, hv.z, acc.z); acc.w = fmaf(p, hv.w, acc.w);
            }
            st4(&PHt[row * 8 + qh], acc);
        }
        __syncwarp();

        // S rows + RHS into registers
        float s4[4], rhs[8];
        {
            const int ch = h * 4;
            s4[0] = Rb[rr * 8 + ch];     s4[1] = Rb[rr * 8 + ch + 1];
            s4[2] = Rb[rr * 8 + ch + 2]; s4[3] = Rb[rr * 8 + ch + 3];
            #pragma unroll
            for (int k = 0; k < 16; ++k) {
                float hv = Hb[rr * 20 + k];
                float4 ph = ld4(&PHt[k * 8 + ch]);
                s4[0] = fmaf(hv, ph.x, s4[0]); s4[1] = fmaf(hv, ph.y, s4[1]);
                s4[2] = fmaf(hv, ph.z, s4[2]); s4[3] = fmaf(hv, ph.w, s4[3]);
            }
            #pragma unroll
            for (int j = 0; j < 8; ++j)
                rhs[j] = PHt[(h * 8 + j) * 8 + rr];
        }

        // GJ solve S * X2 = PHt^T (8x8); K = X2^T
        {
            #pragma unroll
            for (int p = 0; p < 8; ++p) {
                const int hp = (p >= 4) ? 1 : 0;
                float cand = s4[p & 3];
                float f_num = shfl(cand, (rr << 1) | hp);
                float diag  = shfl(cand, (p << 1) | hp);
                const int src = (p << 1) | h;
                float ps0 = shfl(s4[0], src), ps1 = shfl(s4[1], src);
                float ps2 = shfl(s4[2], src), ps3 = shfl(s4[3], src);
                float pr[8];
                #pragma unroll
                for (int j = 0; j < 8; ++j) pr[j] = shfl(rhs[j], src);
                float f = (rr == p) ? 0.0f : f_num * rcpa(diag);
                s4[0] = fmaf(-f, ps0, s4[0]); s4[1] = fmaf(-f, ps1, s4[1]);
                s4[2] = fmaf(-f, ps2, s4[2]); s4[3] = fmaf(-f, ps3, s4[3]);
                #pragma unroll
                for (int j = 0; j < 8; ++j) rhs[j] = fmaf(-f, pr[j], rhs[j]);
            }
            float s01 = (rr & 1) ? s4[1] : s4[0];
            float s23 = (rr & 1) ? s4[3] : s4[2];
            float cand_r = (rr & 2) ? s23 : s01;
            float diag_r = shfl(cand_r, (rr << 1) | ((rr >= 4) ? 1 : 0));
            float invd = rcpa(diag_r);
            if (lane < 16) {
                st4(&X2[rr * 20 + h * 8],
                    make_float4(rhs[0] * invd, rhs[1] * invd, rhs[2] * invd, rhs[3] * invd));
                st4(&X2[rr * 20 + h * 8 + 4],
                    make_float4(rhs[4] * invd, rhs[5] * invd, rhs[6] * invd, rhs[7] * invd));
                #pragma unroll
                for (int j = 0; j < 8; ++j)
                    g_K2[t * 128 + (h * 8 + j) * 8 + rr] = rhs[j] * invd;
            }
        }
        __syncwarp();

        // P_f = PP - K*(H*PP);  (H*PP)[q][j] = PHt[j][q]
        {
            float kq[8];
            #pragma unroll
            for (int q = 0; q < 8; ++q) kq[q] = X2[q * 20 + row];
            float n[8];
            #pragma unroll
            for (int j = 0; j < 8; ++j) {
                float4 p0 = ld4(&PHt[(j0 + j) * 8]);
                float4 p1 = ld4(&PHt[(j0 + j) * 8 + 4]);
                float v = a[j];
                v = fmaf(-kq[0], p0.x, v); v = fmaf(-kq[1], p0.y, v);
                v = fmaf(-kq[2], p0.z, v); v = fmaf(-kq[3], p0.w, v);
                v = fmaf(-kq[4], p1.x, v); v = fmaf(-kq[5], p1.y, v);
                v = fmaf(-kq[6], p1.z, v); v = fmaf(-kq[7], p1.w, v);
                n[j] = v;
            }
            float4 v0 = make_float4(n[0], n[1], n[2], n[3]);
            float4 v1 = make_float4(n[4], n[5], n[6], n[7]);
            st4(&P[row * 20 + j0], v0);
            st4(&P[row * 20 + j0 + 4], v1);
            if (t < T - 1) {
                st4(&g_Pf[t * 256 + row * 16 + j0], v0);
                st4(&g_Pf[t * 256 + row * 16 + j0 + 4], v1);
            }
        }
        __syncwarp();
    }
}

// ============================================================================
// Kernel B: smoother gains (R11). g_G[t][i][j] row-major.
// ============================================================================
__global__ __launch_bounds__(32) void kf_smoother_gains(
    const float* __restrict__ A, const float* __restrict__ Q)
{
    __shared__ float Fb[16 * 20], Ftb[16 * 20], Qb[16 * 20], Pf[16 * 20];
    const int t = blockIdx.x;
    const int lane = threadIdx.x;

    for (int idx = lane; idx < 256; idx += 32) {
        int i = idx >> 4, k = idx & 15;
        float av = A[idx];
        float f = (i == k ? 1.0f : 0.0f) + DT * av;
        Fb[i * 20 + k] = f; Ftb[k * 20 + i] = f;
        Qb[i * 20 + k] = Q[idx];
        Pf[i * 20 + k] = g_Pf[t * 256 + idx];
    }
    __syncwarp();

    const int row = lane >> 1, h = lane & 1, j0 = h * 8;
    float frow[16];
    #pragma unroll
    for (int k = 0; k < 16; ++k) frow[k] = Fb[row * 20 + k];

    float a[8], w[8];
    #pragma unroll
    for (int j = 0; j < 8; ++j) w[j] = 0.0f;
    #pragma unroll
    for (int k = 0; k < 16; ++k) {
        float fv = frow[k];
        float4 p0 = ld4(&Pf[k * 20 + j0]);
        float4 p1 = ld4(&Pf[k * 20 + j0 + 4]);
        w[0] = fmaf(fv, p0.x, w[0]); w[1] = fmaf(fv, p0.y, w[1]);
        w[2] = fmaf(fv, p0.z, w[2]); w[3] = fmaf(fv, p0.w, w[3]);
        w[4] = fmaf(fv, p1.x, w[4]); w[5] = fmaf(fv, p1.y, w[5]);
        w[6] = fmaf(fv, p1.z, w[6]); w[7] = fmaf(fv, p1.w, w[7]);
    }
    {
        float wk[16];
        #pragma unroll
        for (int j = 0; j < 8; ++j) {
            wk[j0 + j] = w[j];
            wk[(j0 ^ 8) + j] = shflx(w[j], 1);
        }
        float4 q0 = ld4(&Qb[row * 20 + j0]);
        float4 q1 = ld4(&Qb[row * 20 + j0 + 4]);
        a[0] = q0.x; a[1] = q0.y; a[2] = q0.z; a[3] = q0.w;
        a[4] = q1.x; a[5] = q1.y; a[6] = q1.z; a[7] = q1.w;
        #pragma unroll
        for (int k = 0; k < 16; ++k) {
            float wv = wk[k];
            float4 f0 = ld4(&Ftb[k * 20 + j0]);
            float4 f1 = ld4(&Ftb[k * 20 + j0 + 4]);
            a[0] = fmaf(wv, f0.x, a[0]); a[1] = fmaf(wv, f0.y, a[1]);
            a[2] = fmaf(wv, f0.z, a[2]); a[3] = fmaf(wv, f0.w, a[3]);
            a[4] = fmaf(wv, f1.x, a[4]); a[5] = fmaf(wv, f1.y, a[5]);
            a[6] = fmaf(wv, f1.z, a[6]); a[7] = fmaf(wv, f1.w, a[7]);
        }
    }
    #pragma unroll
    for (int p = 0; p < 16; ++p) {
        const int hp = (p >= 8) ? 1 : 0;
        float cand = a[p & 7];
        float f_num = shfl(cand, (row << 1) | hp);
        float diag  = shfl(cand, (p << 1) | hp);
        const int src = (p << 1) | h;
        float pa[8], pw[8];
        #pragma unroll
        for (int j = 0; j < 8; ++j) { pa[j] = shfl(a[j], src); pw[j] = shfl(w[j], src); }
        float f = (row == p) ? 0.0f : f_num * rcpa(diag);
        #pragma unroll
        for (int j = 0; j < 8; ++j) {
            a[j] = fmaf(-f, pa[j], a[j]);
            w[j] = fmaf(-f, pw[j], w[j]);
        }
    }
    const int ri = row & 7;
    float s01 = (ri & 1) ? a[1] : a[0];
    float s23 = (ri & 1) ? a[3] : a[2];
    float s45 = (ri & 1) ? a[5] : a[4];
    float s67 = (ri & 1) ? a[7] : a[6];
    float t0 = (ri & 2) ? s23 : s01;
    float t1 = (ri & 2) ? s67 : s45;
    float cand_r = (ri & 4) ? t1 : t0;
    float diag_r = shfl(cand_r, (row << 1) | ((row >= 8) ? 1 : 0));
    float invd = rcpa(diag_r);
    #pragma unroll
    for (int j = 0; j < 8; ++j)
        g_G[t * 256 + (j0 + j) * 16 + row] = w[j] * invd;
}

// ============================================================================
// Kernel C: forward state filter, smem-staged; writes out + g_fp (sf|sp lines).
// ============================================================================
__global__ __launch_bounds__(256) void kf_states(
    const float* __restrict__ state0, const float* __restrict__ controls,
    const float* __restrict__ obs, const float* __restrict__ A,
    const float* __restrict__ Bc, const float* __restrict__ H,
    float* __restrict__ out)
{
    extern __shared__ float sm[];
    float* Ks = sm;
    float* us = Ks + T * 128;
    float* ys = us + SB * T * 4;

    const int tid = threadIdx.x;
    const int b0 = blockIdx.x * SB;

    for (int idx = tid; idx < 4096; idx += 256)
        st4(&Ks[idx * 4], ld4(&g_K2[idx * 4]));
    {
        const float* src = controls + (size_t)b0 * T * 4;
        for (int idx = tid; idx < 2048; idx += 256)
            st4(&us[idx * 4], ld4(&src[idx * 4]));
    }
    {
        const float* src = obs + (size_t)b0 * T * 8;
        for (int idx = tid; idx < 4096; idx += 256)
            st4(&ys[idx * 4], ld4(&src[idx * 4]));
    }
    __syncthreads();

    const int L = tid & 31;
    const int bl = (tid >> 5) * 2 + (L >> 4);
    const int b = b0 + bl;
    const int i = L & 15;

    float arow[16], hrow[16], brow[4];
    #pragma unroll
    for (int k = 0; k < 16; ++k) arow[k] = A[i * 16 + k];
    #pragma unroll
    for (int k = 0; k < 16; ++k) hrow[k] = H[(i & 7) * 16 + k];
    #pragma unroll
    for (int c = 0; c < 4; ++c) brow[c] = Bc[i * 4 + c];

    float s = state0[b * 16 + i];

    #pragma unroll 1
    for (int t = 0; t < T; ++t) {
        float4 uu = ld4(&us[bl * 512 + t * 4]);
        float4 k0 = ld4(&Ks[t * 128 + i * 8]);
        float4 k1 = ld4(&Ks[t * 128 + i * 8 + 4]);
        float yv = ys[bl * 1024 + t * 8 + (i & 7)];

        float a0 = 0.0f, a1 = 0.0f;
        #pragma unroll
        for (int k = 0; k < 8; ++k) {
            a0 = fmaf(arow[k], shfl16(s, k), a0);
            a1 = fmaf(arow[k + 8], shfl16(s, k + 8), a1);
        }
        a0 = fmaf(brow[0], uu.x, a0); a0 = fmaf(brow[1], uu.y, a0);
        a0 = fmaf(brow[2], uu.z, a0); a0 = fmaf(brow[3], uu.w, a0);
        float sp = s + DT * (a0 + a1);
        if (t > 0) g_fp[((size_t)b * T + t) * 32 + 16 + i] = sp;

        float h0 = 0.0f, h1 = 0.0f;
        #pragma unroll
        for (int k = 0; k < 8; ++k) {
            h0 = fmaf(hrow[k], shfl16(sp, k), h0);
            h1 = fmaf(hrow[k + 8], shfl16(sp, k + 8), h1);
        }
        float iv = yv - (h0 + h1);

        float acc = sp;
        acc = fmaf(k0.x, shfl16(iv, 0), acc);
        acc = fmaf(k0.y, shfl16(iv, 1), acc);
        acc = fmaf(k0.z, shfl16(iv, 2), acc);
        acc = fmaf(k0.w, shfl16(iv, 3), acc);
        acc = fmaf(k1.x, shfl16(iv, 4), acc);
        acc = fmaf(k1.y, shfl16(iv, 5), acc);
        acc = fmaf(k1.z, shfl16(iv, 6), acc);
        acc = fmaf(k1.w, shfl16(iv, 7), acc);
        s = acc;
        g_fp[((size_t)b * T + t) * 32 + i] = s;
        out[((size_t)b * T + t) * NS + i] = s;
    }
}

// ============================================================================
// Kernel D: backward smoother. Reads g_fp only, writes out only (no aliasing).
// Prefetch depth 2 on G rows + fp values.
// ============================================================================
__global__ __launch_bounds__(128) void kf_backward(float* __restrict__ out)
{
    const int L = threadIdx.x & 31;
    const int gw = blockIdx.x * 4 + (threadIdx.x >> 5);
    const int b = gw * 2 + (L >> 4);
    const int i = L & 15;
    const size_t bT = (size_t)b * T;

    // init: ss = sf[T-1]; stage c = data for t=T-2; stage n = data for t=T-3
    float ss = g_fp[(bT + T - 1) * 32 + i];
    float spn_c = g_fp[(bT + T - 1) * 32 + 16 + i];   // sp[t+1] for t=T-2
    float sf_c  = g_fp[(bT + T - 2) * 32 + i];        // sf[T-2]
    float xc[16];
    {
        const float* gp = &g_G[(T - 2) * 256 + i * 16];
        float4 g0 = ld4(gp), g1 = ld4(gp + 4), g2 = ld4(gp + 8), g3 = ld4(gp + 12);
        xc[0] = g0.x; xc[1] = g0.y; xc[2] = g0.z; xc[3] = g0.w;
        xc[4] = g1.x; xc[5] = g1.y; xc[6] = g1.z; xc[7] = g1.w;
        xc[8] = g2.x; xc[9] = g2.y; xc[10] = g2.z; xc[11] = g2.w;
        xc[12] = g3.x; xc[13] = g3.y; xc[14] = g3.z; xc[15] = g3.w;
    }
    float spn_n = 0.f, sf_n = 0.f, xn[16];
    if (T - 3 >= 0) {
        spn_n = g_fp[(bT + T - 2) * 32 + 16 + i];
        sf_n  = g_fp[(bT + T - 3) * 32 + i];
        const float* gp = &g_G[(T - 3) * 256 + i * 16];
        float4 g0 = ld4(gp), g1 = ld4(gp + 4), g2 = ld4(gp + 8), g3 = ld4(gp + 12);
        xn[0] = g0.x; xn[1] = g0.y; xn[2] = g0.z; xn[3] = g0.w;
        xn[4] = g1.x; xn[5] = g1.y; xn[6] = g1.z; xn[7] = g1.w;
        xn[8] = g2.x; xn[9] = g2.y; xn[10] = g2.z; xn[11] = g2.w;
        xn[12] = g3.x; xn[13] = g3.y; xn[14] = g3.z; xn[15] = g3.w;
    }

    #pragma unroll 1
    for (int t = T - 2; t >= 0; --t) {
        // fetch data for step t-2 (consumed two iterations from now)
        float spn_f = 0.f, sf_f = 0.f, xf[16];
        if (t - 2 >= 0) {
            spn_f = g_fp[(bT + t - 1) * 32 + 16 + i];
            sf_f  = g_fp[(bT + t - 2) * 32 + i];
            const float* gp = &g_G[(t - 2) * 256 + i * 16];
            float4 g0 = ld4(gp), g1 = ld4(gp + 4), g2 = ld4(gp + 8), g3 = ld4(gp + 12);
            xf[0] = g0.x; xf[1] = g0.y; xf[2] = g0.z; xf[3] = g0.w;
            xf[4] = g1.x; xf[5] = g1.y; xf[6] = g1.z; xf[7] = g1.w;
            xf[8] = g2.x; xf[9] = g2.y; xf[10] = g2.z; xf[11] = g2.w;
            xf[12] = g3.x; xf[13] = g3.y; xf[14] = g3.z; xf[15] = g3.w;
        }

        float d = ss - spn_c;
        float m0 = 0.0f, m1 = 0.0f;
        #pragma unroll
        for (int j = 0; j < 8; ++j) {
            m0 = fmaf(shfl16(d, j), xc[j], m0);
            m1 = fmaf(shfl16(d, j + 8), xc[j + 8], m1);
        }
        ss = sf_c + m0 + m1;
        out[(bT + t) * NS + i] = ss;

        // rotate: c <- n <- f
        #pragma unroll
        for (int j = 0; j < 16; ++j) { xc[j] = xn[j]; xn[j] = xf[j]; }
        spn_c = spn_n; spn_n = spn_f;
        sf_c = sf_n;  sf_n = sf_f;
    }
}

extern "C" void kernel_launch(void* const* d_in, const int* in_sizes, int n_in,
                              void* d_out, int out_size) {
    (void)in_sizes; (void)n_in; (void)out_size;
    const float* state0   = (const float*)d_in[0];
    const float* P0       = (const float*)d_in[1];
    const float* controls = (const float*)d_in[2];
    const float* obs      = (const float*)d_in[3];
    const float* A        = (const float*)d_in[4];
    const float* Bc       = (const float*)d_in[5];
    const float* H        = (const float*)d_in[6];
    const float* Q        = (const float*)d_in[7];
    const float* R        = (const float*)d_in[8];
    float* out = (float*)d_out;

    const int smem_states = (T * 128 + SB * T * 4 + SB * T * 8) * 4;   // 163840 B
    cudaFuncSetAttribute(kf_states, cudaFuncAttributeMaxDynamicSharedMemorySize, smem_states);

    kf_gains<<<1, 32>>>(P0, A, H, Q, R);
    kf_smoother_gains<<<T - 1, 32>>>(A, Q);
    kf_states<<<BATCH / SB, 256, smem_states>>>(state0, controls, obs, A, Bc, H, out);
    kf_backward<<<BATCH / 8, 128>>>(out);
}